// round 12
// baseline (speedup 1.0000x reference)
#include <cuda_runtime.h>
#include <cuda_bf16.h>
#include <cuda_fp16.h>
#include <math.h>
#include <cstdint>

#define B_      2
#define S_      2048
#define D_      4096
#define NH_     32
#define NKV_    8
#define HD_     128
#define TOK_    (B_ * S_)          // 4096 tokens
#define NQKV_   6144               // NH*HD + 2*NKV*HD

// ---------------------------------------------------------------------------
// Scratch (static device globals — no runtime allocation)
// ---------------------------------------------------------------------------
__device__ float g_QKV[(size_t)TOK_ * NQKV_];       // fused QKV fp32, row stride 6144

__device__ __half g_Ah[(size_t)TOK_ * D_];          // hidden fp16
__device__ __half g_Wh[(size_t)NQKV_ * D_];         // wq|wk|wv fp16
__device__ __half g_WOh[(size_t)D_ * NH_ * HD_];    // wo fp16
__device__ __half g_Ohf[(size_t)TOK_ * NH_ * HD_];  // attention out fp16
__device__ __half g_Qh[(size_t)TOK_ * NH_ * HD_];   // roped+scaled Q fp16
__device__ __half g_Kh[(size_t)TOK_ * NKV_ * HD_];  // roped K fp16
__device__ __half g_Vh[(size_t)TOK_ * NKV_ * HD_];  // V fp16

// ---------------------------------------------------------------------------
// helpers (target-portable: no sm_103a-only features)
// ---------------------------------------------------------------------------
__device__ __forceinline__ uint32_t smem_u32(const void* p) {
    uint32_t a;
    asm("{ .reg .u64 t; cvta.to.shared.u64 t, %1; cvt.u32.u64 %0, t; }" : "=r"(a) : "l"(p));
    return a;
}
__device__ __forceinline__ void cp_async16(uint32_t s, const void* g) {
    asm volatile("cp.async.cg.shared.global [%0], [%1], 16;"
                 :: "r"(s), "l"(__cvta_generic_to_global(g)) : "memory");
}
__device__ __forceinline__ void cp_commit() {
    asm volatile("cp.async.commit_group;" ::: "memory");
}
__device__ __forceinline__ void cp_wait0() {
    asm volatile("cp.async.wait_group 0;" ::: "memory");
}
__device__ __forceinline__ void ldmx4(uint32_t& r0, uint32_t& r1, uint32_t& r2,
                                      uint32_t& r3, uint32_t addr) {
    asm volatile("ldmatrix.sync.aligned.m8n8.x4.shared.b16 {%0,%1,%2,%3}, [%4];"
                 : "=r"(r0), "=r"(r1), "=r"(r2), "=r"(r3) : "r"(addr));
}
__device__ __forceinline__ void ldmx4t(uint32_t& r0, uint32_t& r1, uint32_t& r2,
                                       uint32_t& r3, uint32_t addr) {
    asm volatile("ldmatrix.sync.aligned.m8n8.x4.trans.shared.b16 {%0,%1,%2,%3}, [%4];"
                 : "=r"(r0), "=r"(r1), "=r"(r2), "=r"(r3) : "r"(addr));
}
__device__ __forceinline__ void mma16816h(float* c, uint32_t a0, uint32_t a1,
                                          uint32_t a2, uint32_t a3,
                                          uint32_t b0, uint32_t b1) {
    asm volatile(
        "mma.sync.aligned.m16n8k16.row.col.f32.f16.f16.f32 "
        "{%0,%1,%2,%3}, {%4,%5,%6,%7}, {%8,%9}, {%0,%1,%2,%3};"
        : "+f"(c[0]), "+f"(c[1]), "+f"(c[2]), "+f"(c[3])
        : "r"(a0), "r"(a1), "r"(a2), "r"(a3), "r"(b0), "r"(b1));
}
__device__ __forceinline__ float ex2f(float x) {
    float y; asm("ex2.approx.f32 %0, %1;" : "=f"(y) : "f"(x)); return y;
}

// ---------------------------------------------------------------------------
// GEMM: C[M,N] fp32 = A[M,K](fp16) * B[N,K](fp16)^T  (unchanged from R7)
// ---------------------------------------------------------------------------
#define STRIDE_B  80
#define TILE_B    (128 * STRIDE_B)     // 10240
#define GBUF      (2 * TILE_B)         // 20480
#define GEMM_DYNSMEM (2 * GBUF)        // 40960

__device__ __forceinline__ void issue_chunk16(
    uint32_t buf, const __half* A, const __half* Bw, int K, int kbyte, int tid)
{
    #pragma unroll
    for (int p = 0; p < 2; p++) {
        int c  = tid + p * 256;
        int r  = c >> 2;
        int cb = (c & 3) << 4;
        size_t go = (size_t)r * (K * 2) + kbyte + cb;
        uint32_t so = r * STRIDE_B + cb;
        cp_async16(buf + so,          (const char*)A  + go);
        cp_async16(buf + TILE_B + so, (const char*)Bw + go);
    }
}

__global__ __launch_bounds__(256, 2) void gemm_f16(
    const __half* __restrict__ A, const __half* __restrict__ Bw,
    float* __restrict__ C, int M, int N, int K)
{
    extern __shared__ char dynsm[];
    const uint32_t smem = smem_u32(dynsm);

    const int tid  = threadIdx.x;
    const int wid  = tid >> 5;
    const int lane = tid & 31;
    const int m0 = blockIdx.y * 128;
    const int n0 = blockIdx.x * 128;
    const int m0w = (wid >> 2) * 64;
    const int n0w = (wid & 3) * 32;

    const __half* pA = A  + (size_t)m0 * K;
    const __half* pB = Bw + (size_t)n0 * K;

    float acc[4][4][4];
    #pragma unroll
    for (int i = 0; i < 4; i++)
        #pragma unroll
        for (int j = 0; j < 4; j++)
            #pragma unroll
            for (int q = 0; q < 4; q++) acc[i][j][q] = 0.f;

    const int NCH = K >> 5;

    issue_chunk16(smem, pA, pB, K, 0, tid);
    cp_commit();
    cp_wait0();
    __syncthreads();

    const uint32_t lrow = (uint32_t)(lane & 15) * STRIDE_B;
    const uint32_t lcol = (uint32_t)(lane >> 4) * 16;

    for (int i = 0; i < NCH; i++) {
        const uint32_t buf = smem + (uint32_t)(i & 1) * GBUF;
        if (i + 1 < NCH) {
            issue_chunk16(smem + (uint32_t)((i + 1) & 1) * GBUF,
                          pA, pB, K, (i + 1) * 64, tid);
        }
        cp_commit();

        const uint32_t aBase = buf + (uint32_t)m0w * STRIDE_B + lrow + lcol;
        const uint32_t bBase = buf + TILE_B + (uint32_t)n0w * STRIDE_B + lrow + lcol;

        #pragma unroll
        for (int ks = 0; ks < 2; ks++) {
            const uint32_t kb = (uint32_t)ks * 32;

            uint32_t bh[2][4];
            #pragma unroll
            for (int np = 0; np < 2; np++) {
                uint32_t off = (uint32_t)np * 16 * STRIDE_B + kb;
                ldmx4(bh[np][0], bh[np][1], bh[np][2], bh[np][3], bBase + off);
            }

            #pragma unroll
            for (int mt = 0; mt < 4; mt++) {
                uint32_t off = (uint32_t)mt * 16 * STRIDE_B + kb;
                uint32_t a0, a1, a2, a3;
                ldmx4(a0, a1, a2, a3, aBase + off);

                #pragma unroll
                for (int nt = 0; nt < 4; nt++) {
                    const int np = nt >> 1, sel = nt & 1;
                    mma16816h(acc[mt][nt], a0, a1, a2, a3,
                              bh[np][sel], bh[np][sel + 2]);
                }
            }
        }
        cp_wait0();
        __syncthreads();
    }

    const int rbase = m0 + m0w + (lane >> 2);
    const int cbase = n0 + n0w + (lane & 3) * 2;
    #pragma unroll
    for (int mt = 0; mt < 4; mt++) {
        #pragma unroll
        for (int nt = 0; nt < 4; nt++) {
            float* c0 = C + (size_t)(rbase + mt * 16) * N + cbase + nt * 8;
            float* c1 = C + (size_t)(rbase + mt * 16 + 8) * N + cbase + nt * 8;
            c0[0] = acc[mt][nt][0]; c0[1] = acc[mt][nt][1];
            c1[0] = acc[mt][nt][2]; c1[1] = acc[mt][nt][3];
        }
    }
}

// ---------------------------------------------------------------------------
// fp32 -> fp16 convert
// ---------------------------------------------------------------------------
__global__ void conv_f16(const float* __restrict__ x, __half* __restrict__ y, int n)
{
    int i = blockIdx.x * blockDim.x + threadIdx.x;
    if (i < n) y[i] = __float2half_rn(x[i]);
}

// ---------------------------------------------------------------------------
// Fused: RoPE+scale Q -> Qh fp16; RoPE K -> Kh fp16; V -> Vh fp16.
// One thread per (tok, unit u in [0,48), d in [0,64)).
// ---------------------------------------------------------------------------
__global__ void rope_pack(const float* __restrict__ QKV,
                          const float* __restrict__ cosp,
                          const float* __restrict__ sinp,
                          __half* __restrict__ Qh,
                          __half* __restrict__ Kh,
                          __half* __restrict__ Vh)
{
    const float SC = 0.08838834764831845f * 1.4426950408889634f;
    int idx = blockIdx.x * blockDim.x + threadIdx.x;
    int d   = idx & 63;
    int u   = (idx >> 6) % 48;
    int tok = idx / (64 * 48);
    if (tok >= TOK_) return;

    if (u < NH_) {                         // Q: rope + scale
        float c = cosp[(size_t)tok * HD_ + d];
        float s = sinp[(size_t)tok * HD_ + d];
        const float* row = QKV + (size_t)tok * NQKV_ + u * HD_;
        float x1 = row[d], x2 = row[d + 64];
        __half* q = Qh + ((size_t)tok * NH_ + u) * HD_;
        q[d]      = __float2half_rn((x1 * c - x2 * s) * SC);
        q[d + 64] = __float2half_rn((x2 * c + x1 * s) * SC);
    } else if (u < NH_ + NKV_) {           // K: rope
        int kh = u - NH_;
        float c = cosp[(size_t)tok * HD_ + d];
        float s = sinp[(size_t)tok * HD_ + d];
        const float* row = QKV + (size_t)tok * NQKV_ + (NH_ + kh) * HD_;
        float x1 = row[d], x2 = row[d + 64];
        __half* k = Kh + ((size_t)tok * NKV_ + kh) * HD_;
        k[d]      = __float2half_rn(x1 * c - x2 * s);
        k[d + 64] = __float2half_rn(x2 * c + x1 * s);
    } else {                               // V: convert
        int kh = u - NH_ - NKV_;
        const float* row = QKV + (size_t)tok * NQKV_ + (NH_ + NKV_ + kh) * HD_;
        __half* v = Vh + ((size_t)tok * NKV_ + kh) * HD_;
        v[d]      = __float2half_rn(row[d]);
        v[d + 64] = __float2half_rn(row[d + 64]);
    }
}

// ---------------------------------------------------------------------------
// FlashAttention-2-style causal GQA attention, single-term fp16 mma.sync.
// CTA = 128 q rows of one (b,h); 8 warps x 16 rows; 64-key double-buffered
// K/V; Q fragments hoisted to registers; fp32 softmax in log2 domain.
// ---------------------------------------------------------------------------
#define ATT_STRIDE 272u
#define ATT_QT     34816u        // 128*272
#define ATT_KT     17408u        // 64*272
#define ATT_SMEM   104448        // QT + 2*KT(K) + 2*KT(V)

__global__ __launch_bounds__(256) void attn_f16(
    const __half* __restrict__ Qh, const __half* __restrict__ Kh,
    const __half* __restrict__ Vh, __half* __restrict__ Ohf)
{
    extern __shared__ char sm[];
    const uint32_t sb = smem_u32(sm);
    const uint32_t sQ = sb;
    const uint32_t sK = sb + ATT_QT;
    const uint32_t sV = sK + 2 * ATT_KT;

    const int tid = threadIdx.x, wid = tid >> 5, lane = tid & 31;
    const int qb = gridDim.x - 1 - blockIdx.x;      // big blocks first
    const int h = blockIdx.y, b = blockIdx.z, kh = h >> 2;
    const int nkt = 2 * qb + 2;

    auto loadkv = [&](int t, uint32_t kbuf, uint32_t vbuf) {
        #pragma unroll
        for (int j = 0; j < 4; j++) {
            int c = tid + j * 256;
            int r = c >> 4, cb = (c & 15) << 4;
            size_t g = (((size_t)(b * S_ + t * 64 + r)) * NKV_ + kh) * (HD_ * 2) + cb;
            uint32_t so = (uint32_t)r * ATT_STRIDE + cb;
            cp_async16(kbuf + so, (const char*)Kh + g);
            cp_async16(vbuf + so, (const char*)Vh + g);
        }
    };

    // Q tile: 128 rows x 256B, strided rows from packed Qh
    {
        const char* qg = (const char*)(Qh + (((size_t)(b * S_ + qb * 128)) * NH_ + h) * HD_);
        #pragma unroll
        for (int j = 0; j < 8; j++) {
            int c = tid + j * 256;
            int r = c >> 4, cb = (c & 15) << 4;
            cp_async16(sQ + (uint32_t)r * ATT_STRIDE + cb,
                       qg + (size_t)r * (NH_ * HD_ * 2) + cb);
        }
    }
    loadkv(0, sK, sV);
    cp_commit();
    cp_wait0();
    __syncthreads();

    const uint32_t lrow = (uint32_t)(lane & 15) * ATT_STRIDE + (uint32_t)(lane >> 4) * 16;

    // hoist Q fragments (16 rows per warp, full HD=128)
    uint32_t qf[8][4];
    {
        const uint32_t qBase = sQ + (uint32_t)(wid * 16) * ATT_STRIDE + lrow;
        #pragma unroll
        for (int ks = 0; ks < 8; ks++)
            ldmx4(qf[ks][0], qf[ks][1], qf[ks][2], qf[ks][3], qBase + ks * 32);
    }

    float out[16][4];
    #pragma unroll
    for (int i = 0; i < 16; i++)
        #pragma unroll
        for (int j = 0; j < 4; j++) out[i][j] = 0.f;
    float mr0 = -INFINITY, mr1 = -INFINITY, lr0 = 0.f, lr1 = 0.f;

    const int rowA = qb * 128 + wid * 16 + (lane >> 2);

    for (int t = 0; t < nkt; t++) {
        const uint32_t kb = sK + (uint32_t)(t & 1) * ATT_KT;
        const uint32_t vb = sV + (uint32_t)(t & 1) * ATT_KT;
        if (t + 1 < nkt)
            loadkv(t + 1, sK + (uint32_t)((t + 1) & 1) * ATT_KT,
                          sV + (uint32_t)((t + 1) & 1) * ATT_KT);
        cp_commit();

        const bool active = (t * 64 <= qb * 128 + wid * 16 + 15);
        if (active) {
            // ---- scores: S = Q K^T ----
            float s[8][4];
            #pragma unroll
            for (int i = 0; i < 8; i++)
                #pragma unroll
                for (int j = 0; j < 4; j++) s[i][j] = 0.f;

            #pragma unroll
            for (int ks = 0; ks < 8; ks++) {
                #pragma unroll
                for (int g = 0; g < 4; g++) {
                    const uint32_t koff = (uint32_t)(g * 16) * ATT_STRIDE + lrow + ks * 32;
                    uint32_t b0, b1, b2, b3;
                    ldmx4(b0, b1, b2, b3, kb + koff);
                    mma16816h(s[2*g],   qf[ks][0], qf[ks][1], qf[ks][2], qf[ks][3], b0, b2);
                    mma16816h(s[2*g+1], qf[ks][0], qf[ks][1], qf[ks][2], qf[ks][3], b1, b3);
                }
            }

            // ---- causal mask near diagonal ----
            if (t * 64 + 63 > qb * 128 + wid * 16) {
                const int cb0 = t * 64 + (lane & 3) * 2;
                #pragma unroll
                for (int nt = 0; nt < 8; nt++) {
                    const int c0i = cb0 + nt * 8;
                    if (c0i     > rowA)     s[nt][0] = -INFINITY;
                    if (c0i + 1 > rowA)     s[nt][1] = -INFINITY;
                    if (c0i     > rowA + 8) s[nt][2] = -INFINITY;
                    if (c0i + 1 > rowA + 8) s[nt][3] = -INFINITY;
                }
            }

            // ---- online softmax (log2 domain) ----
            float mA = -INFINITY, mB = -INFINITY;
            #pragma unroll
            for (int nt = 0; nt < 8; nt++) {
                mA = fmaxf(mA, fmaxf(s[nt][0], s[nt][1]));
                mB = fmaxf(mB, fmaxf(s[nt][2], s[nt][3]));
            }
            mA = fmaxf(mA, __shfl_xor_sync(0xffffffffu, mA, 1));
            mA = fmaxf(mA, __shfl_xor_sync(0xffffffffu, mA, 2));
            mB = fmaxf(mB, __shfl_xor_sync(0xffffffffu, mB, 1));
            mB = fmaxf(mB, __shfl_xor_sync(0xffffffffu, mB, 2));
            const float mn0 = fmaxf(mr0, mA), mn1 = fmaxf(mr1, mB);
            const float cr0 = ex2f(mr0 - mn0), cr1 = ex2f(mr1 - mn1);
            mr0 = mn0; mr1 = mn1;

            float ps0 = 0.f, ps1 = 0.f;
            #pragma unroll
            for (int nt = 0; nt < 8; nt++) {
                s[nt][0] = ex2f(s[nt][0] - mn0); ps0 += s[nt][0];
                s[nt][1] = ex2f(s[nt][1] - mn0); ps0 += s[nt][1];
                s[nt][2] = ex2f(s[nt][2] - mn1); ps1 += s[nt][2];
                s[nt][3] = ex2f(s[nt][3] - mn1); ps1 += s[nt][3];
            }
            ps0 += __shfl_xor_sync(0xffffffffu, ps0, 1);
            ps0 += __shfl_xor_sync(0xffffffffu, ps0, 2);
            ps1 += __shfl_xor_sync(0xffffffffu, ps1, 1);
            ps1 += __shfl_xor_sync(0xffffffffu, ps1, 2);
            lr0 = lr0 * cr0 + ps0;
            lr1 = lr1 * cr1 + ps1;
            #pragma unroll
            for (int i = 0; i < 16; i++) {
                out[i][0] *= cr0; out[i][1] *= cr0;
                out[i][2] *= cr1; out[i][3] *= cr1;
            }

            // ---- PV: out += P V ----
            #pragma unroll
            for (int kt = 0; kt < 4; kt++) {
                uint32_t pH[4];
                {
                    __half2 h0 = __floats2half2_rn(s[2*kt][0],   s[2*kt][1]);
                    __half2 h1 = __floats2half2_rn(s[2*kt][2],   s[2*kt][3]);
                    __half2 h2 = __floats2half2_rn(s[2*kt+1][0], s[2*kt+1][1]);
                    __half2 h3 = __floats2half2_rn(s[2*kt+1][2], s[2*kt+1][3]);
                    pH[0] = *(uint32_t*)&h0; pH[1] = *(uint32_t*)&h1;
                    pH[2] = *(uint32_t*)&h2; pH[3] = *(uint32_t*)&h3;
                }
                #pragma unroll
                for (int dg = 0; dg < 8; dg++) {
                    const uint32_t voff =
                        (uint32_t)(kt * 16 + (lane & 7) + ((lane >> 3) & 1) * 8) * ATT_STRIDE
                        + (uint32_t)(dg * 16 + (lane >> 4) * 8) * 2;
                    uint32_t v0, v1, v2, v3;
                    ldmx4t(v0, v1, v2, v3, vb + voff);
                    mma16816h(out[2*dg],   pH[0], pH[1], pH[2], pH[3], v0, v1);
                    mma16816h(out[2*dg+1], pH[0], pH[1], pH[2], pH[3], v2, v3);
                }
            }
        }
        cp_wait0();
        __syncthreads();
    }

    // ---- epilogue: normalize, store fp16 ----
    const float i0 = 1.f / lr0, i1 = 1.f / lr1;
    const size_t oA = (((size_t)b * S_ + rowA) * NH_ + h) * HD_;
    const size_t oB = oA + (size_t)8 * NH_ * HD_;
    #pragma unroll
    for (int nt = 0; nt < 16; nt++) {
        const int col = nt * 8 + (lane & 3) * 2;
        __half2 ha = __floats2half2_rn(out[nt][0] * i0, out[nt][1] * i0);
        __half2 hb = __floats2half2_rn(out[nt][2] * i1, out[nt][3] * i1);
        *(uint32_t*)(Ohf + oA + col) = *(uint32_t*)&ha;
        *(uint32_t*)(Ohf + oB + col) = *(uint32_t*)&hb;
    }
}

// ---------------------------------------------------------------------------
// kernel_launch — inputs: hidden_states, cos, sin, wq, wk, wv, wo
// ---------------------------------------------------------------------------
extern "C" void kernel_launch(void* const* d_in, const int* in_sizes, int n_in,
                              void* d_out, int out_size)
{
    const float* hidden = (const float*)d_in[0];
    const float* cosp   = (const float*)d_in[1];
    const float* sinp   = (const float*)d_in[2];
    const float* wq     = (const float*)d_in[3];
    const float* wk     = (const float*)d_in[4];
    const float* wv     = (const float*)d_in[5];
    const float* wo     = (const float*)d_in[6];
    float* out = (float*)d_out;

    float* QKV;
    cudaGetSymbolAddress((void**)&QKV, g_QKV);
    __half *Ah, *Wh, *WOh, *Ohf, *Qh, *Kh, *Vh;
    cudaGetSymbolAddress((void**)&Ah, g_Ah);
    cudaGetSymbolAddress((void**)&Wh, g_Wh);
    cudaGetSymbolAddress((void**)&WOh, g_WOh);
    cudaGetSymbolAddress((void**)&Ohf, g_Ohf);
    cudaGetSymbolAddress((void**)&Qh, g_Qh);
    cudaGetSymbolAddress((void**)&Kh, g_Kh);
    cudaGetSymbolAddress((void**)&Vh, g_Vh);

    cudaFuncSetAttribute(gemm_f16, cudaFuncAttributeMaxDynamicSharedMemorySize,
                         GEMM_DYNSMEM);
    cudaFuncSetAttribute(attn_f16, cudaFuncAttributeMaxDynamicSharedMemorySize,
                         ATT_SMEM);

    // fp16 converts: hidden, concatenated qkv weights, wo
    {
        int n;
        n = TOK_ * D_;       conv_f16<<<(n + 255) / 256, 256>>>(hidden, Ah, n);
        n = NH_ * HD_ * D_;  conv_f16<<<(n + 255) / 256, 256>>>(wq, Wh, n);
        n = NKV_ * HD_ * D_;
        conv_f16<<<(n + 255) / 256, 256>>>(wk, Wh + (size_t)NH_ * HD_ * D_, n);
        conv_f16<<<(n + 255) / 256, 256>>>(wv, Wh + (size_t)(NH_ + NKV_) * HD_ * D_, n);
        n = D_ * NH_ * HD_;  conv_f16<<<(n + 255) / 256, 256>>>(wo, WOh, n);
    }

    // Fused QKV projection (fp16 single-term)
    gemm_f16<<<dim3(NQKV_ / 128, TOK_ / 128), 256, GEMM_DYNSMEM>>>(
        Ah, Wh, QKV, TOK_, NQKV_, D_);

    // Fused RoPE + fp16 pack of Q/K/V
    rope_pack<<<(TOK_ * 48 * 64) / 256, 256>>>(QKV, cosp, sinp, Qh, Kh, Vh);

    // Attention (single-term fp16) -> Ohf
    attn_f16<<<dim3(S_ / 128, NH_, B_), 256, ATT_SMEM>>>(Qh, Kh, Vh, Ohf);

    // Output projection (fp16 single-term)
    gemm_f16<<<dim3(D_ / 128, TOK_ / 128), 256, GEMM_DYNSMEM>>>(
        Ohf, WOh, out, TOK_, D_, NH_ * HD_);
}

// round 13
// speedup vs baseline: 1.0034x; 1.0034x over previous
#include <cuda_runtime.h>
#include <cuda_bf16.h>
#include <cuda_fp16.h>
#include <math.h>
#include <cstdint>

#define B_      2
#define S_      2048
#define D_      4096
#define NH_     32
#define NKV_    8
#define HD_     128
#define TOK_    (B_ * S_)          // 4096 tokens
#define NQKV_   6144               // NH*HD + 2*NKV*HD

// ---------------------------------------------------------------------------
// Scratch (static device globals — no runtime allocation)
// ---------------------------------------------------------------------------
__device__ float g_QKV[(size_t)TOK_ * NQKV_];       // fused QKV fp32, row stride 6144

__device__ __half g_Ah[(size_t)TOK_ * D_];          // hidden fp16
__device__ __half g_Wh[(size_t)NQKV_ * D_];         // wq|wk|wv fp16
__device__ __half g_WOh[(size_t)D_ * NH_ * HD_];    // wo fp16
__device__ __half g_Ohf[(size_t)TOK_ * NH_ * HD_];  // attention out fp16
__device__ __half g_Qh[(size_t)TOK_ * NH_ * HD_];   // roped+scaled Q fp16
__device__ __half g_Kh[(size_t)TOK_ * NKV_ * HD_];  // roped K fp16
__device__ __half g_Vh[(size_t)TOK_ * NKV_ * HD_];  // V fp16

// ---------------------------------------------------------------------------
// helpers (target-portable: no sm_103a-only features)
// ---------------------------------------------------------------------------
__device__ __forceinline__ uint32_t smem_u32(const void* p) {
    uint32_t a;
    asm("{ .reg .u64 t; cvta.to.shared.u64 t, %1; cvt.u32.u64 %0, t; }" : "=r"(a) : "l"(p));
    return a;
}
__device__ __forceinline__ void cp_async16(uint32_t s, const void* g) {
    asm volatile("cp.async.cg.shared.global [%0], [%1], 16;"
                 :: "r"(s), "l"(__cvta_generic_to_global(g)) : "memory");
}
__device__ __forceinline__ void cp_commit() {
    asm volatile("cp.async.commit_group;" ::: "memory");
}
__device__ __forceinline__ void cp_wait0() {
    asm volatile("cp.async.wait_group 0;" ::: "memory");
}
__device__ __forceinline__ void ldmx4(uint32_t& r0, uint32_t& r1, uint32_t& r2,
                                      uint32_t& r3, uint32_t addr) {
    asm volatile("ldmatrix.sync.aligned.m8n8.x4.shared.b16 {%0,%1,%2,%3}, [%4];"
                 : "=r"(r0), "=r"(r1), "=r"(r2), "=r"(r3) : "r"(addr));
}
__device__ __forceinline__ void ldmx4t(uint32_t& r0, uint32_t& r1, uint32_t& r2,
                                       uint32_t& r3, uint32_t addr) {
    asm volatile("ldmatrix.sync.aligned.m8n8.x4.trans.shared.b16 {%0,%1,%2,%3}, [%4];"
                 : "=r"(r0), "=r"(r1), "=r"(r2), "=r"(r3) : "r"(addr));
}
__device__ __forceinline__ void mma16816h(float* c, uint32_t a0, uint32_t a1,
                                          uint32_t a2, uint32_t a3,
                                          uint32_t b0, uint32_t b1) {
    asm volatile(
        "mma.sync.aligned.m16n8k16.row.col.f32.f16.f16.f32 "
        "{%0,%1,%2,%3}, {%4,%5,%6,%7}, {%8,%9}, {%0,%1,%2,%3};"
        : "+f"(c[0]), "+f"(c[1]), "+f"(c[2]), "+f"(c[3])
        : "r"(a0), "r"(a1), "r"(a2), "r"(a3), "r"(b0), "r"(b1));
}
__device__ __forceinline__ float ex2f(float x) {
    float y; asm("ex2.approx.f32 %0, %1;" : "=f"(y) : "f"(x)); return y;
}

// ---------------------------------------------------------------------------
// GEMM: C[M,N] fp32 = A[M,K](fp16) * B[N,K](fp16)^T  (unchanged from R7)
// ---------------------------------------------------------------------------
#define STRIDE_B  80
#define TILE_B    (128 * STRIDE_B)     // 10240
#define GBUF      (2 * TILE_B)         // 20480
#define GEMM_DYNSMEM (2 * GBUF)        // 40960

__device__ __forceinline__ void issue_chunk16(
    uint32_t buf, const __half* A, const __half* Bw, int K, int kbyte, int tid)
{
    #pragma unroll
    for (int p = 0; p < 2; p++) {
        int c  = tid + p * 256;
        int r  = c >> 2;
        int cb = (c & 3) << 4;
        size_t go = (size_t)r * (K * 2) + kbyte + cb;
        uint32_t so = r * STRIDE_B + cb;
        cp_async16(buf + so,          (const char*)A  + go);
        cp_async16(buf + TILE_B + so, (const char*)Bw + go);
    }
}

__global__ __launch_bounds__(256, 2) void gemm_f16(
    const __half* __restrict__ A, const __half* __restrict__ Bw,
    float* __restrict__ C, int M, int N, int K)
{
    extern __shared__ char dynsm[];
    const uint32_t smem = smem_u32(dynsm);

    const int tid  = threadIdx.x;
    const int wid  = tid >> 5;
    const int lane = tid & 31;
    const int m0 = blockIdx.y * 128;
    const int n0 = blockIdx.x * 128;
    const int m0w = (wid >> 2) * 64;
    const int n0w = (wid & 3) * 32;

    const __half* pA = A  + (size_t)m0 * K;
    const __half* pB = Bw + (size_t)n0 * K;

    float acc[4][4][4];
    #pragma unroll
    for (int i = 0; i < 4; i++)
        #pragma unroll
        for (int j = 0; j < 4; j++)
            #pragma unroll
            for (int q = 0; q < 4; q++) acc[i][j][q] = 0.f;

    const int NCH = K >> 5;

    issue_chunk16(smem, pA, pB, K, 0, tid);
    cp_commit();
    cp_wait0();
    __syncthreads();

    const uint32_t lrow = (uint32_t)(lane & 15) * STRIDE_B;
    const uint32_t lcol = (uint32_t)(lane >> 4) * 16;

    for (int i = 0; i < NCH; i++) {
        const uint32_t buf = smem + (uint32_t)(i & 1) * GBUF;
        if (i + 1 < NCH) {
            issue_chunk16(smem + (uint32_t)((i + 1) & 1) * GBUF,
                          pA, pB, K, (i + 1) * 64, tid);
        }
        cp_commit();

        const uint32_t aBase = buf + (uint32_t)m0w * STRIDE_B + lrow + lcol;
        const uint32_t bBase = buf + TILE_B + (uint32_t)n0w * STRIDE_B + lrow + lcol;

        #pragma unroll
        for (int ks = 0; ks < 2; ks++) {
            const uint32_t kb = (uint32_t)ks * 32;

            uint32_t bh[2][4];
            #pragma unroll
            for (int np = 0; np < 2; np++) {
                uint32_t off = (uint32_t)np * 16 * STRIDE_B + kb;
                ldmx4(bh[np][0], bh[np][1], bh[np][2], bh[np][3], bBase + off);
            }

            #pragma unroll
            for (int mt = 0; mt < 4; mt++) {
                uint32_t off = (uint32_t)mt * 16 * STRIDE_B + kb;
                uint32_t a0, a1, a2, a3;
                ldmx4(a0, a1, a2, a3, aBase + off);

                #pragma unroll
                for (int nt = 0; nt < 4; nt++) {
                    const int np = nt >> 1, sel = nt & 1;
                    mma16816h(acc[mt][nt], a0, a1, a2, a3,
                              bh[np][sel], bh[np][sel + 2]);
                }
            }
        }
        cp_wait0();
        __syncthreads();
    }

    const int rbase = m0 + m0w + (lane >> 2);
    const int cbase = n0 + n0w + (lane & 3) * 2;
    #pragma unroll
    for (int mt = 0; mt < 4; mt++) {
        #pragma unroll
        for (int nt = 0; nt < 4; nt++) {
            float* c0 = C + (size_t)(rbase + mt * 16) * N + cbase + nt * 8;
            float* c1 = C + (size_t)(rbase + mt * 16 + 8) * N + cbase + nt * 8;
            c0[0] = acc[mt][nt][0]; c0[1] = acc[mt][nt][1];
            c1[0] = acc[mt][nt][2]; c1[1] = acc[mt][nt][3];
        }
    }
}

// ---------------------------------------------------------------------------
// fp32 -> fp16 convert
// ---------------------------------------------------------------------------
__global__ void conv_f16(const float* __restrict__ x, __half* __restrict__ y, int n)
{
    int i = blockIdx.x * blockDim.x + threadIdx.x;
    if (i < n) y[i] = __float2half_rn(x[i]);
}

// ---------------------------------------------------------------------------
// Fused: RoPE+scale Q -> Qh fp16; RoPE K -> Kh fp16; V -> Vh fp16.
// One thread per (tok, unit u in [0,48), d in [0,64)).
// ---------------------------------------------------------------------------
__global__ void rope_pack(const float* __restrict__ QKV,
                          const float* __restrict__ cosp,
                          const float* __restrict__ sinp,
                          __half* __restrict__ Qh,
                          __half* __restrict__ Kh,
                          __half* __restrict__ Vh)
{
    const float SC = 0.08838834764831845f * 1.4426950408889634f;
    int idx = blockIdx.x * blockDim.x + threadIdx.x;
    int d   = idx & 63;
    int u   = (idx >> 6) % 48;
    int tok = idx / (64 * 48);
    if (tok >= TOK_) return;

    if (u < NH_) {                         // Q: rope + scale
        float c = cosp[(size_t)tok * HD_ + d];
        float s = sinp[(size_t)tok * HD_ + d];
        const float* row = QKV + (size_t)tok * NQKV_ + u * HD_;
        float x1 = row[d], x2 = row[d + 64];
        __half* q = Qh + ((size_t)tok * NH_ + u) * HD_;
        q[d]      = __float2half_rn((x1 * c - x2 * s) * SC);
        q[d + 64] = __float2half_rn((x2 * c + x1 * s) * SC);
    } else if (u < NH_ + NKV_) {           // K: rope
        int kh = u - NH_;
        float c = cosp[(size_t)tok * HD_ + d];
        float s = sinp[(size_t)tok * HD_ + d];
        const float* row = QKV + (size_t)tok * NQKV_ + (NH_ + kh) * HD_;
        float x1 = row[d], x2 = row[d + 64];
        __half* k = Kh + ((size_t)tok * NKV_ + kh) * HD_;
        k[d]      = __float2half_rn(x1 * c - x2 * s);
        k[d + 64] = __float2half_rn(x2 * c + x1 * s);
    } else {                               // V: convert
        int kh = u - NH_ - NKV_;
        const float* row = QKV + (size_t)tok * NQKV_ + (NH_ + NKV_ + kh) * HD_;
        __half* v = Vh + ((size_t)tok * NKV_ + kh) * HD_;
        v[d]      = __float2half_rn(row[d]);
        v[d + 64] = __float2half_rn(row[d + 64]);
    }
}

// ---------------------------------------------------------------------------
// FlashAttention-2-style causal GQA attention, single-term fp16 mma.sync.
// CTA = 128 q rows of one (b,h); 8 warps x 16 rows; 64-key double-buffered
// K/V; Q fragments hoisted to registers; fp32 softmax in log2 domain.
// ---------------------------------------------------------------------------
#define ATT_STRIDE 272u
#define ATT_QT     34816u        // 128*272
#define ATT_KT     17408u        // 64*272
#define ATT_SMEM   104448        // QT + 2*KT(K) + 2*KT(V)

__global__ __launch_bounds__(256) void attn_f16(
    const __half* __restrict__ Qh, const __half* __restrict__ Kh,
    const __half* __restrict__ Vh, __half* __restrict__ Ohf)
{
    extern __shared__ char sm[];
    const uint32_t sb = smem_u32(sm);
    const uint32_t sQ = sb;
    const uint32_t sK = sb + ATT_QT;
    const uint32_t sV = sK + 2 * ATT_KT;

    const int tid = threadIdx.x, wid = tid >> 5, lane = tid & 31;
    const int qb = gridDim.x - 1 - blockIdx.x;      // big blocks first
    const int h = blockIdx.y, b = blockIdx.z, kh = h >> 2;
    const int nkt = 2 * qb + 2;

    auto loadkv = [&](int t, uint32_t kbuf, uint32_t vbuf) {
        #pragma unroll
        for (int j = 0; j < 4; j++) {
            int c = tid + j * 256;
            int r = c >> 4, cb = (c & 15) << 4;
            size_t g = (((size_t)(b * S_ + t * 64 + r)) * NKV_ + kh) * (HD_ * 2) + cb;
            uint32_t so = (uint32_t)r * ATT_STRIDE + cb;
            cp_async16(kbuf + so, (const char*)Kh + g);
            cp_async16(vbuf + so, (const char*)Vh + g);
        }
    };

    // Q tile: 128 rows x 256B, strided rows from packed Qh
    {
        const char* qg = (const char*)(Qh + (((size_t)(b * S_ + qb * 128)) * NH_ + h) * HD_);
        #pragma unroll
        for (int j = 0; j < 8; j++) {
            int c = tid + j * 256;
            int r = c >> 4, cb = (c & 15) << 4;
            cp_async16(sQ + (uint32_t)r * ATT_STRIDE + cb,
                       qg + (size_t)r * (NH_ * HD_ * 2) + cb);
        }
    }
    loadkv(0, sK, sV);
    cp_commit();
    cp_wait0();
    __syncthreads();

    const uint32_t lrow = (uint32_t)(lane & 15) * ATT_STRIDE + (uint32_t)(lane >> 4) * 16;

    // hoist Q fragments (16 rows per warp, full HD=128)
    uint32_t qf[8][4];
    {
        const uint32_t qBase = sQ + (uint32_t)(wid * 16) * ATT_STRIDE + lrow;
        #pragma unroll
        for (int ks = 0; ks < 8; ks++)
            ldmx4(qf[ks][0], qf[ks][1], qf[ks][2], qf[ks][3], qBase + ks * 32);
    }

    float out[16][4];
    #pragma unroll
    for (int i = 0; i < 16; i++)
        #pragma unroll
        for (int j = 0; j < 4; j++) out[i][j] = 0.f;
    float mr0 = -INFINITY, mr1 = -INFINITY, lr0 = 0.f, lr1 = 0.f;

    const int rowA = qb * 128 + wid * 16 + (lane >> 2);

    for (int t = 0; t < nkt; t++) {
        const uint32_t kb = sK + (uint32_t)(t & 1) * ATT_KT;
        const uint32_t vb = sV + (uint32_t)(t & 1) * ATT_KT;
        if (t + 1 < nkt)
            loadkv(t + 1, sK + (uint32_t)((t + 1) & 1) * ATT_KT,
                          sV + (uint32_t)((t + 1) & 1) * ATT_KT);
        cp_commit();

        const bool active = (t * 64 <= qb * 128 + wid * 16 + 15);
        if (active) {
            // ---- scores: S = Q K^T ----
            float s[8][4];
            #pragma unroll
            for (int i = 0; i < 8; i++)
                #pragma unroll
                for (int j = 0; j < 4; j++) s[i][j] = 0.f;

            #pragma unroll
            for (int ks = 0; ks < 8; ks++) {
                #pragma unroll
                for (int g = 0; g < 4; g++) {
                    const uint32_t koff = (uint32_t)(g * 16) * ATT_STRIDE + lrow + ks * 32;
                    uint32_t b0, b1, b2, b3;
                    ldmx4(b0, b1, b2, b3, kb + koff);
                    mma16816h(s[2*g],   qf[ks][0], qf[ks][1], qf[ks][2], qf[ks][3], b0, b2);
                    mma16816h(s[2*g+1], qf[ks][0], qf[ks][1], qf[ks][2], qf[ks][3], b1, b3);
                }
            }

            // ---- causal mask near diagonal ----
            if (t * 64 + 63 > qb * 128 + wid * 16) {
                const int cb0 = t * 64 + (lane & 3) * 2;
                #pragma unroll
                for (int nt = 0; nt < 8; nt++) {
                    const int c0i = cb0 + nt * 8;
                    if (c0i     > rowA)     s[nt][0] = -INFINITY;
                    if (c0i + 1 > rowA)     s[nt][1] = -INFINITY;
                    if (c0i     > rowA + 8) s[nt][2] = -INFINITY;
                    if (c0i + 1 > rowA + 8) s[nt][3] = -INFINITY;
                }
            }

            // ---- online softmax (log2 domain) ----
            float mA = -INFINITY, mB = -INFINITY;
            #pragma unroll
            for (int nt = 0; nt < 8; nt++) {
                mA = fmaxf(mA, fmaxf(s[nt][0], s[nt][1]));
                mB = fmaxf(mB, fmaxf(s[nt][2], s[nt][3]));
            }
            mA = fmaxf(mA, __shfl_xor_sync(0xffffffffu, mA, 1));
            mA = fmaxf(mA, __shfl_xor_sync(0xffffffffu, mA, 2));
            mB = fmaxf(mB, __shfl_xor_sync(0xffffffffu, mB, 1));
            mB = fmaxf(mB, __shfl_xor_sync(0xffffffffu, mB, 2));
            const float mn0 = fmaxf(mr0, mA), mn1 = fmaxf(mr1, mB);
            const float cr0 = ex2f(mr0 - mn0), cr1 = ex2f(mr1 - mn1);
            mr0 = mn0; mr1 = mn1;

            float ps0 = 0.f, ps1 = 0.f;
            #pragma unroll
            for (int nt = 0; nt < 8; nt++) {
                s[nt][0] = ex2f(s[nt][0] - mn0); ps0 += s[nt][0];
                s[nt][1] = ex2f(s[nt][1] - mn0); ps0 += s[nt][1];
                s[nt][2] = ex2f(s[nt][2] - mn1); ps1 += s[nt][2];
                s[nt][3] = ex2f(s[nt][3] - mn1); ps1 += s[nt][3];
            }
            ps0 += __shfl_xor_sync(0xffffffffu, ps0, 1);
            ps0 += __shfl_xor_sync(0xffffffffu, ps0, 2);
            ps1 += __shfl_xor_sync(0xffffffffu, ps1, 1);
            ps1 += __shfl_xor_sync(0xffffffffu, ps1, 2);
            lr0 = lr0 * cr0 + ps0;
            lr1 = lr1 * cr1 + ps1;
            #pragma unroll
            for (int i = 0; i < 16; i++) {
                out[i][0] *= cr0; out[i][1] *= cr0;
                out[i][2] *= cr1; out[i][3] *= cr1;
            }

            // ---- PV: out += P V ----
            #pragma unroll
            for (int kt = 0; kt < 4; kt++) {
                uint32_t pH[4];
                {
                    __half2 h0 = __floats2half2_rn(s[2*kt][0],   s[2*kt][1]);
                    __half2 h1 = __floats2half2_rn(s[2*kt][2],   s[2*kt][3]);
                    __half2 h2 = __floats2half2_rn(s[2*kt+1][0], s[2*kt+1][1]);
                    __half2 h3 = __floats2half2_rn(s[2*kt+1][2], s[2*kt+1][3]);
                    pH[0] = *(uint32_t*)&h0; pH[1] = *(uint32_t*)&h1;
                    pH[2] = *(uint32_t*)&h2; pH[3] = *(uint32_t*)&h3;
                }
                #pragma unroll
                for (int dg = 0; dg < 8; dg++) {
                    const uint32_t voff =
                        (uint32_t)(kt * 16 + (lane & 7) + ((lane >> 3) & 1) * 8) * ATT_STRIDE
                        + (uint32_t)(dg * 16 + (lane >> 4) * 8) * 2;
                    uint32_t v0, v1, v2, v3;
                    ldmx4t(v0, v1, v2, v3, vb + voff);
                    mma16816h(out[2*dg],   pH[0], pH[1], pH[2], pH[3], v0, v1);
                    mma16816h(out[2*dg+1], pH[0], pH[1], pH[2], pH[3], v2, v3);
                }
            }
        }
        cp_wait0();
        __syncthreads();
    }

    // ---- epilogue: normalize, store fp16 ----
    const float i0 = 1.f / lr0, i1 = 1.f / lr1;
    const size_t oA = (((size_t)b * S_ + rowA) * NH_ + h) * HD_;
    const size_t oB = oA + (size_t)8 * NH_ * HD_;
    #pragma unroll
    for (int nt = 0; nt < 16; nt++) {
        const int col = nt * 8 + (lane & 3) * 2;
        __half2 ha = __floats2half2_rn(out[nt][0] * i0, out[nt][1] * i0);
        __half2 hb = __floats2half2_rn(out[nt][2] * i1, out[nt][3] * i1);
        *(uint32_t*)(Ohf + oA + col) = *(uint32_t*)&ha;
        *(uint32_t*)(Ohf + oB + col) = *(uint32_t*)&hb;
    }
}

// ---------------------------------------------------------------------------
// kernel_launch — inputs: hidden_states, cos, sin, wq, wk, wv, wo
// ---------------------------------------------------------------------------
extern "C" void kernel_launch(void* const* d_in, const int* in_sizes, int n_in,
                              void* d_out, int out_size)
{
    const float* hidden = (const float*)d_in[0];
    const float* cosp   = (const float*)d_in[1];
    const float* sinp   = (const float*)d_in[2];
    const float* wq     = (const float*)d_in[3];
    const float* wk     = (const float*)d_in[4];
    const float* wv     = (const float*)d_in[5];
    const float* wo     = (const float*)d_in[6];
    float* out = (float*)d_out;

    float* QKV;
    cudaGetSymbolAddress((void**)&QKV, g_QKV);
    __half *Ah, *Wh, *WOh, *Ohf, *Qh, *Kh, *Vh;
    cudaGetSymbolAddress((void**)&Ah, g_Ah);
    cudaGetSymbolAddress((void**)&Wh, g_Wh);
    cudaGetSymbolAddress((void**)&WOh, g_WOh);
    cudaGetSymbolAddress((void**)&Ohf, g_Ohf);
    cudaGetSymbolAddress((void**)&Qh, g_Qh);
    cudaGetSymbolAddress((void**)&Kh, g_Kh);
    cudaGetSymbolAddress((void**)&Vh, g_Vh);

    cudaFuncSetAttribute(gemm_f16, cudaFuncAttributeMaxDynamicSharedMemorySize,
                         GEMM_DYNSMEM);
    cudaFuncSetAttribute(attn_f16, cudaFuncAttributeMaxDynamicSharedMemorySize,
                         ATT_SMEM);

    // fp16 converts: hidden, concatenated qkv weights, wo
    {
        int n;
        n = TOK_ * D_;       conv_f16<<<(n + 255) / 256, 256>>>(hidden, Ah, n);
        n = NH_ * HD_ * D_;  conv_f16<<<(n + 255) / 256, 256>>>(wq, Wh, n);
        n = NKV_ * HD_ * D_;
        conv_f16<<<(n + 255) / 256, 256>>>(wk, Wh + (size_t)NH_ * HD_ * D_, n);
        conv_f16<<<(n + 255) / 256, 256>>>(wv, Wh + (size_t)(NH_ + NKV_) * HD_ * D_, n);
        n = D_ * NH_ * HD_;  conv_f16<<<(n + 255) / 256, 256>>>(wo, WOh, n);
    }

    // Fused QKV projection (fp16 single-term)
    gemm_f16<<<dim3(NQKV_ / 128, TOK_ / 128), 256, GEMM_DYNSMEM>>>(
        Ah, Wh, QKV, TOK_, NQKV_, D_);

    // Fused RoPE + fp16 pack of Q/K/V
    rope_pack<<<(TOK_ * 48 * 64) / 256, 256>>>(QKV, cosp, sinp, Qh, Kh, Vh);

    // Attention (single-term fp16) -> Ohf
    attn_f16<<<dim3(S_ / 128, NH_, B_), 256, ATT_SMEM>>>(Qh, Kh, Vh, Ohf);

    // Output projection (fp16 single-term)
    gemm_f16<<<dim3(D_ / 128, TOK_ / 128), 256, GEMM_DYNSMEM>>>(
        Ohf, WOh, out, TOK_, D_, NH_ * HD_);
}

// round 14
// speedup vs baseline: 1.0049x; 1.0015x over previous
#include <cuda_runtime.h>
#include <cuda_bf16.h>
#include <cuda_fp16.h>
#include <math.h>
#include <cstdint>

#define B_      2
#define S_      2048
#define D_      4096
#define NH_     32
#define NKV_    8
#define HD_     128
#define TOK_    (B_ * S_)          // 4096 tokens
#define NQKV_   6144               // NH*HD + 2*NKV*HD

// ---------------------------------------------------------------------------
// Scratch (static device globals — no runtime allocation)
// ---------------------------------------------------------------------------
__device__ float g_QKV[(size_t)TOK_ * NQKV_];       // fused QKV fp32, row stride 6144

__device__ __half g_Ah[(size_t)TOK_ * D_];          // hidden fp16
__device__ __half g_Wh[(size_t)NQKV_ * D_];         // wq|wk|wv fp16
__device__ __half g_WOh[(size_t)D_ * NH_ * HD_];    // wo fp16
__device__ __half g_Ohf[(size_t)TOK_ * NH_ * HD_];  // attention out fp16
__device__ __half g_Qh[(size_t)TOK_ * NH_ * HD_];   // roped+scaled Q fp16
__device__ __half g_Kh[(size_t)TOK_ * NKV_ * HD_];  // roped K fp16
__device__ __half g_Vh[(size_t)TOK_ * NKV_ * HD_];  // V fp16

// ---------------------------------------------------------------------------
// helpers (target-portable: no sm_103a-only features)
// ---------------------------------------------------------------------------
__device__ __forceinline__ uint32_t smem_u32(const void* p) {
    uint32_t a;
    asm("{ .reg .u64 t; cvta.to.shared.u64 t, %1; cvt.u32.u64 %0, t; }" : "=r"(a) : "l"(p));
    return a;
}
__device__ __forceinline__ void cp_async16(uint32_t s, const void* g) {
    asm volatile("cp.async.cg.shared.global [%0], [%1], 16;"
                 :: "r"(s), "l"(__cvta_generic_to_global(g)) : "memory");
}
__device__ __forceinline__ void cp_commit() {
    asm volatile("cp.async.commit_group;" ::: "memory");
}
__device__ __forceinline__ void cp_wait0() {
    asm volatile("cp.async.wait_group 0;" ::: "memory");
}
__device__ __forceinline__ void ldmx4(uint32_t& r0, uint32_t& r1, uint32_t& r2,
                                      uint32_t& r3, uint32_t addr) {
    asm volatile("ldmatrix.sync.aligned.m8n8.x4.shared.b16 {%0,%1,%2,%3}, [%4];"
                 : "=r"(r0), "=r"(r1), "=r"(r2), "=r"(r3) : "r"(addr));
}
__device__ __forceinline__ void ldmx4t(uint32_t& r0, uint32_t& r1, uint32_t& r2,
                                       uint32_t& r3, uint32_t addr) {
    asm volatile("ldmatrix.sync.aligned.m8n8.x4.trans.shared.b16 {%0,%1,%2,%3}, [%4];"
                 : "=r"(r0), "=r"(r1), "=r"(r2), "=r"(r3) : "r"(addr));
}
__device__ __forceinline__ void mma16816h(float* c, uint32_t a0, uint32_t a1,
                                          uint32_t a2, uint32_t a3,
                                          uint32_t b0, uint32_t b1) {
    asm volatile(
        "mma.sync.aligned.m16n8k16.row.col.f32.f16.f16.f32 "
        "{%0,%1,%2,%3}, {%4,%5,%6,%7}, {%8,%9}, {%0,%1,%2,%3};"
        : "+f"(c[0]), "+f"(c[1]), "+f"(c[2]), "+f"(c[3])
        : "r"(a0), "r"(a1), "r"(a2), "r"(a3), "r"(b0), "r"(b1));
}
__device__ __forceinline__ float ex2f(float x) {
    float y; asm("ex2.approx.f32 %0, %1;" : "=f"(y) : "f"(x)); return y;
}

// ---------------------------------------------------------------------------
// GEMM: C[M,N] fp32 = A[M,K](fp16) * B[N,K](fp16)^T  (unchanged from R7)
// ---------------------------------------------------------------------------
#define STRIDE_B  80
#define TILE_B    (128 * STRIDE_B)     // 10240
#define GBUF      (2 * TILE_B)         // 20480
#define GEMM_DYNSMEM (2 * GBUF)        // 40960

__device__ __forceinline__ void issue_chunk16(
    uint32_t buf, const __half* A, const __half* Bw, int K, int kbyte, int tid)
{
    #pragma unroll
    for (int p = 0; p < 2; p++) {
        int c  = tid + p * 256;
        int r  = c >> 2;
        int cb = (c & 3) << 4;
        size_t go = (size_t)r * (K * 2) + kbyte + cb;
        uint32_t so = r * STRIDE_B + cb;
        cp_async16(buf + so,          (const char*)A  + go);
        cp_async16(buf + TILE_B + so, (const char*)Bw + go);
    }
}

__global__ __launch_bounds__(256, 2) void gemm_f16(
    const __half* __restrict__ A, const __half* __restrict__ Bw,
    float* __restrict__ C, int M, int N, int K)
{
    extern __shared__ char dynsm[];
    const uint32_t smem = smem_u32(dynsm);

    const int tid  = threadIdx.x;
    const int wid  = tid >> 5;
    const int lane = tid & 31;
    const int m0 = blockIdx.y * 128;
    const int n0 = blockIdx.x * 128;
    const int m0w = (wid >> 2) * 64;
    const int n0w = (wid & 3) * 32;

    const __half* pA = A  + (size_t)m0 * K;
    const __half* pB = Bw + (size_t)n0 * K;

    float acc[4][4][4];
    #pragma unroll
    for (int i = 0; i < 4; i++)
        #pragma unroll
        for (int j = 0; j < 4; j++)
            #pragma unroll
            for (int q = 0; q < 4; q++) acc[i][j][q] = 0.f;

    const int NCH = K >> 5;

    issue_chunk16(smem, pA, pB, K, 0, tid);
    cp_commit();
    cp_wait0();
    __syncthreads();

    const uint32_t lrow = (uint32_t)(lane & 15) * STRIDE_B;
    const uint32_t lcol = (uint32_t)(lane >> 4) * 16;

    for (int i = 0; i < NCH; i++) {
        const uint32_t buf = smem + (uint32_t)(i & 1) * GBUF;
        if (i + 1 < NCH) {
            issue_chunk16(smem + (uint32_t)((i + 1) & 1) * GBUF,
                          pA, pB, K, (i + 1) * 64, tid);
        }
        cp_commit();

        const uint32_t aBase = buf + (uint32_t)m0w * STRIDE_B + lrow + lcol;
        const uint32_t bBase = buf + TILE_B + (uint32_t)n0w * STRIDE_B + lrow + lcol;

        #pragma unroll
        for (int ks = 0; ks < 2; ks++) {
            const uint32_t kb = (uint32_t)ks * 32;

            uint32_t bh[2][4];
            #pragma unroll
            for (int np = 0; np < 2; np++) {
                uint32_t off = (uint32_t)np * 16 * STRIDE_B + kb;
                ldmx4(bh[np][0], bh[np][1], bh[np][2], bh[np][3], bBase + off);
            }

            #pragma unroll
            for (int mt = 0; mt < 4; mt++) {
                uint32_t off = (uint32_t)mt * 16 * STRIDE_B + kb;
                uint32_t a0, a1, a2, a3;
                ldmx4(a0, a1, a2, a3, aBase + off);

                #pragma unroll
                for (int nt = 0; nt < 4; nt++) {
                    const int np = nt >> 1, sel = nt & 1;
                    mma16816h(acc[mt][nt], a0, a1, a2, a3,
                              bh[np][sel], bh[np][sel + 2]);
                }
            }
        }
        cp_wait0();
        __syncthreads();
    }

    const int rbase = m0 + m0w + (lane >> 2);
    const int cbase = n0 + n0w + (lane & 3) * 2;
    #pragma unroll
    for (int mt = 0; mt < 4; mt++) {
        #pragma unroll
        for (int nt = 0; nt < 4; nt++) {
            float* c0 = C + (size_t)(rbase + mt * 16) * N + cbase + nt * 8;
            float* c1 = C + (size_t)(rbase + mt * 16 + 8) * N + cbase + nt * 8;
            c0[0] = acc[mt][nt][0]; c0[1] = acc[mt][nt][1];
            c1[0] = acc[mt][nt][2]; c1[1] = acc[mt][nt][3];
        }
    }
}

// ---------------------------------------------------------------------------
// fp32 -> fp16 convert
// ---------------------------------------------------------------------------
__global__ void conv_f16(const float* __restrict__ x, __half* __restrict__ y, int n)
{
    int i = blockIdx.x * blockDim.x + threadIdx.x;
    if (i < n) y[i] = __float2half_rn(x[i]);
}

// ---------------------------------------------------------------------------
// Fused: RoPE+scale Q -> Qh fp16; RoPE K -> Kh fp16; V -> Vh fp16.
// One thread per (tok, unit u in [0,48), d in [0,64)).
// ---------------------------------------------------------------------------
__global__ void rope_pack(const float* __restrict__ QKV,
                          const float* __restrict__ cosp,
                          const float* __restrict__ sinp,
                          __half* __restrict__ Qh,
                          __half* __restrict__ Kh,
                          __half* __restrict__ Vh)
{
    const float SC = 0.08838834764831845f * 1.4426950408889634f;
    int idx = blockIdx.x * blockDim.x + threadIdx.x;
    int d   = idx & 63;
    int u   = (idx >> 6) % 48;
    int tok = idx / (64 * 48);
    if (tok >= TOK_) return;

    if (u < NH_) {                         // Q: rope + scale
        float c = cosp[(size_t)tok * HD_ + d];
        float s = sinp[(size_t)tok * HD_ + d];
        const float* row = QKV + (size_t)tok * NQKV_ + u * HD_;
        float x1 = row[d], x2 = row[d + 64];
        __half* q = Qh + ((size_t)tok * NH_ + u) * HD_;
        q[d]      = __float2half_rn((x1 * c - x2 * s) * SC);
        q[d + 64] = __float2half_rn((x2 * c + x1 * s) * SC);
    } else if (u < NH_ + NKV_) {           // K: rope
        int kh = u - NH_;
        float c = cosp[(size_t)tok * HD_ + d];
        float s = sinp[(size_t)tok * HD_ + d];
        const float* row = QKV + (size_t)tok * NQKV_ + (NH_ + kh) * HD_;
        float x1 = row[d], x2 = row[d + 64];
        __half* k = Kh + ((size_t)tok * NKV_ + kh) * HD_;
        k[d]      = __float2half_rn(x1 * c - x2 * s);
        k[d + 64] = __float2half_rn(x2 * c + x1 * s);
    } else {                               // V: convert
        int kh = u - NH_ - NKV_;
        const float* row = QKV + (size_t)tok * NQKV_ + (NH_ + NKV_ + kh) * HD_;
        __half* v = Vh + ((size_t)tok * NKV_ + kh) * HD_;
        v[d]      = __float2half_rn(row[d]);
        v[d + 64] = __float2half_rn(row[d + 64]);
    }
}

// ---------------------------------------------------------------------------
// FlashAttention-2-style causal GQA attention, single-term fp16 mma.sync.
// CTA = 128 q rows of one (b,h); 8 warps x 16 rows; 64-key double-buffered
// K/V; Q fragments hoisted to registers; fp32 softmax in log2 domain.
// ---------------------------------------------------------------------------
#define ATT_STRIDE 272u
#define ATT_QT     34816u        // 128*272
#define ATT_KT     17408u        // 64*272
#define ATT_SMEM   104448        // QT + 2*KT(K) + 2*KT(V)

__global__ __launch_bounds__(256) void attn_f16(
    const __half* __restrict__ Qh, const __half* __restrict__ Kh,
    const __half* __restrict__ Vh, __half* __restrict__ Ohf)
{
    extern __shared__ char sm[];
    const uint32_t sb = smem_u32(sm);
    const uint32_t sQ = sb;
    const uint32_t sK = sb + ATT_QT;
    const uint32_t sV = sK + 2 * ATT_KT;

    const int tid = threadIdx.x, wid = tid >> 5, lane = tid & 31;
    const int qb = gridDim.x - 1 - blockIdx.x;      // big blocks first
    const int h = blockIdx.y, b = blockIdx.z, kh = h >> 2;
    const int nkt = 2 * qb + 2;

    auto loadkv = [&](int t, uint32_t kbuf, uint32_t vbuf) {
        #pragma unroll
        for (int j = 0; j < 4; j++) {
            int c = tid + j * 256;
            int r = c >> 4, cb = (c & 15) << 4;
            size_t g = (((size_t)(b * S_ + t * 64 + r)) * NKV_ + kh) * (HD_ * 2) + cb;
            uint32_t so = (uint32_t)r * ATT_STRIDE + cb;
            cp_async16(kbuf + so, (const char*)Kh + g);
            cp_async16(vbuf + so, (const char*)Vh + g);
        }
    };

    // Q tile: 128 rows x 256B, strided rows from packed Qh
    {
        const char* qg = (const char*)(Qh + (((size_t)(b * S_ + qb * 128)) * NH_ + h) * HD_);
        #pragma unroll
        for (int j = 0; j < 8; j++) {
            int c = tid + j * 256;
            int r = c >> 4, cb = (c & 15) << 4;
            cp_async16(sQ + (uint32_t)r * ATT_STRIDE + cb,
                       qg + (size_t)r * (NH_ * HD_ * 2) + cb);
        }
    }
    loadkv(0, sK, sV);
    cp_commit();
    cp_wait0();
    __syncthreads();

    const uint32_t lrow = (uint32_t)(lane & 15) * ATT_STRIDE + (uint32_t)(lane >> 4) * 16;

    // hoist Q fragments (16 rows per warp, full HD=128)
    uint32_t qf[8][4];
    {
        const uint32_t qBase = sQ + (uint32_t)(wid * 16) * ATT_STRIDE + lrow;
        #pragma unroll
        for (int ks = 0; ks < 8; ks++)
            ldmx4(qf[ks][0], qf[ks][1], qf[ks][2], qf[ks][3], qBase + ks * 32);
    }

    float out[16][4];
    #pragma unroll
    for (int i = 0; i < 16; i++)
        #pragma unroll
        for (int j = 0; j < 4; j++) out[i][j] = 0.f;
    float mr0 = -INFINITY, mr1 = -INFINITY, lr0 = 0.f, lr1 = 0.f;

    const int rowA = qb * 128 + wid * 16 + (lane >> 2);

    for (int t = 0; t < nkt; t++) {
        const uint32_t kb = sK + (uint32_t)(t & 1) * ATT_KT;
        const uint32_t vb = sV + (uint32_t)(t & 1) * ATT_KT;
        if (t + 1 < nkt)
            loadkv(t + 1, sK + (uint32_t)((t + 1) & 1) * ATT_KT,
                          sV + (uint32_t)((t + 1) & 1) * ATT_KT);
        cp_commit();

        const bool active = (t * 64 <= qb * 128 + wid * 16 + 15);
        if (active) {
            // ---- scores: S = Q K^T ----
            float s[8][4];
            #pragma unroll
            for (int i = 0; i < 8; i++)
                #pragma unroll
                for (int j = 0; j < 4; j++) s[i][j] = 0.f;

            #pragma unroll
            for (int ks = 0; ks < 8; ks++) {
                #pragma unroll
                for (int g = 0; g < 4; g++) {
                    const uint32_t koff = (uint32_t)(g * 16) * ATT_STRIDE + lrow + ks * 32;
                    uint32_t b0, b1, b2, b3;
                    ldmx4(b0, b1, b2, b3, kb + koff);
                    mma16816h(s[2*g],   qf[ks][0], qf[ks][1], qf[ks][2], qf[ks][3], b0, b2);
                    mma16816h(s[2*g+1], qf[ks][0], qf[ks][1], qf[ks][2], qf[ks][3], b1, b3);
                }
            }

            // ---- causal mask near diagonal ----
            if (t * 64 + 63 > qb * 128 + wid * 16) {
                const int cb0 = t * 64 + (lane & 3) * 2;
                #pragma unroll
                for (int nt = 0; nt < 8; nt++) {
                    const int c0i = cb0 + nt * 8;
                    if (c0i     > rowA)     s[nt][0] = -INFINITY;
                    if (c0i + 1 > rowA)     s[nt][1] = -INFINITY;
                    if (c0i     > rowA + 8) s[nt][2] = -INFINITY;
                    if (c0i + 1 > rowA + 8) s[nt][3] = -INFINITY;
                }
            }

            // ---- online softmax (log2 domain) ----
            float mA = -INFINITY, mB = -INFINITY;
            #pragma unroll
            for (int nt = 0; nt < 8; nt++) {
                mA = fmaxf(mA, fmaxf(s[nt][0], s[nt][1]));
                mB = fmaxf(mB, fmaxf(s[nt][2], s[nt][3]));
            }
            mA = fmaxf(mA, __shfl_xor_sync(0xffffffffu, mA, 1));
            mA = fmaxf(mA, __shfl_xor_sync(0xffffffffu, mA, 2));
            mB = fmaxf(mB, __shfl_xor_sync(0xffffffffu, mB, 1));
            mB = fmaxf(mB, __shfl_xor_sync(0xffffffffu, mB, 2));
            const float mn0 = fmaxf(mr0, mA), mn1 = fmaxf(mr1, mB);
            const float cr0 = ex2f(mr0 - mn0), cr1 = ex2f(mr1 - mn1);
            mr0 = mn0; mr1 = mn1;

            float ps0 = 0.f, ps1 = 0.f;
            #pragma unroll
            for (int nt = 0; nt < 8; nt++) {
                s[nt][0] = ex2f(s[nt][0] - mn0); ps0 += s[nt][0];
                s[nt][1] = ex2f(s[nt][1] - mn0); ps0 += s[nt][1];
                s[nt][2] = ex2f(s[nt][2] - mn1); ps1 += s[nt][2];
                s[nt][3] = ex2f(s[nt][3] - mn1); ps1 += s[nt][3];
            }
            ps0 += __shfl_xor_sync(0xffffffffu, ps0, 1);
            ps0 += __shfl_xor_sync(0xffffffffu, ps0, 2);
            ps1 += __shfl_xor_sync(0xffffffffu, ps1, 1);
            ps1 += __shfl_xor_sync(0xffffffffu, ps1, 2);
            lr0 = lr0 * cr0 + ps0;
            lr1 = lr1 * cr1 + ps1;
            #pragma unroll
            for (int i = 0; i < 16; i++) {
                out[i][0] *= cr0; out[i][1] *= cr0;
                out[i][2] *= cr1; out[i][3] *= cr1;
            }

            // ---- PV: out += P V ----
            #pragma unroll
            for (int kt = 0; kt < 4; kt++) {
                uint32_t pH[4];
                {
                    __half2 h0 = __floats2half2_rn(s[2*kt][0],   s[2*kt][1]);
                    __half2 h1 = __floats2half2_rn(s[2*kt][2],   s[2*kt][3]);
                    __half2 h2 = __floats2half2_rn(s[2*kt+1][0], s[2*kt+1][1]);
                    __half2 h3 = __floats2half2_rn(s[2*kt+1][2], s[2*kt+1][3]);
                    pH[0] = *(uint32_t*)&h0; pH[1] = *(uint32_t*)&h1;
                    pH[2] = *(uint32_t*)&h2; pH[3] = *(uint32_t*)&h3;
                }
                #pragma unroll
                for (int dg = 0; dg < 8; dg++) {
                    const uint32_t voff =
                        (uint32_t)(kt * 16 + (lane & 7) + ((lane >> 3) & 1) * 8) * ATT_STRIDE
                        + (uint32_t)(dg * 16 + (lane >> 4) * 8) * 2;
                    uint32_t v0, v1, v2, v3;
                    ldmx4t(v0, v1, v2, v3, vb + voff);
                    mma16816h(out[2*dg],   pH[0], pH[1], pH[2], pH[3], v0, v1);
                    mma16816h(out[2*dg+1], pH[0], pH[1], pH[2], pH[3], v2, v3);
                }
            }
        }
        cp_wait0();
        __syncthreads();
    }

    // ---- epilogue: normalize, store fp16 ----
    const float i0 = 1.f / lr0, i1 = 1.f / lr1;
    const size_t oA = (((size_t)b * S_ + rowA) * NH_ + h) * HD_;
    const size_t oB = oA + (size_t)8 * NH_ * HD_;
    #pragma unroll
    for (int nt = 0; nt < 16; nt++) {
        const int col = nt * 8 + (lane & 3) * 2;
        __half2 ha = __floats2half2_rn(out[nt][0] * i0, out[nt][1] * i0);
        __half2 hb = __floats2half2_rn(out[nt][2] * i1, out[nt][3] * i1);
        *(uint32_t*)(Ohf + oA + col) = *(uint32_t*)&ha;
        *(uint32_t*)(Ohf + oB + col) = *(uint32_t*)&hb;
    }
}

// ---------------------------------------------------------------------------
// kernel_launch — inputs: hidden_states, cos, sin, wq, wk, wv, wo
// ---------------------------------------------------------------------------
extern "C" void kernel_launch(void* const* d_in, const int* in_sizes, int n_in,
                              void* d_out, int out_size)
{
    const float* hidden = (const float*)d_in[0];
    const float* cosp   = (const float*)d_in[1];
    const float* sinp   = (const float*)d_in[2];
    const float* wq     = (const float*)d_in[3];
    const float* wk     = (const float*)d_in[4];
    const float* wv     = (const float*)d_in[5];
    const float* wo     = (const float*)d_in[6];
    float* out = (float*)d_out;

    float* QKV;
    cudaGetSymbolAddress((void**)&QKV, g_QKV);
    __half *Ah, *Wh, *WOh, *Ohf, *Qh, *Kh, *Vh;
    cudaGetSymbolAddress((void**)&Ah, g_Ah);
    cudaGetSymbolAddress((void**)&Wh, g_Wh);
    cudaGetSymbolAddress((void**)&WOh, g_WOh);
    cudaGetSymbolAddress((void**)&Ohf, g_Ohf);
    cudaGetSymbolAddress((void**)&Qh, g_Qh);
    cudaGetSymbolAddress((void**)&Kh, g_Kh);
    cudaGetSymbolAddress((void**)&Vh, g_Vh);

    cudaFuncSetAttribute(gemm_f16, cudaFuncAttributeMaxDynamicSharedMemorySize,
                         GEMM_DYNSMEM);
    cudaFuncSetAttribute(attn_f16, cudaFuncAttributeMaxDynamicSharedMemorySize,
                         ATT_SMEM);

    // fp16 converts: hidden, concatenated qkv weights, wo
    {
        int n;
        n = TOK_ * D_;       conv_f16<<<(n + 255) / 256, 256>>>(hidden, Ah, n);
        n = NH_ * HD_ * D_;  conv_f16<<<(n + 255) / 256, 256>>>(wq, Wh, n);
        n = NKV_ * HD_ * D_;
        conv_f16<<<(n + 255) / 256, 256>>>(wk, Wh + (size_t)NH_ * HD_ * D_, n);
        conv_f16<<<(n + 255) / 256, 256>>>(wv, Wh + (size_t)(NH_ + NKV_) * HD_ * D_, n);
        n = D_ * NH_ * HD_;  conv_f16<<<(n + 255) / 256, 256>>>(wo, WOh, n);
    }

    // Fused QKV projection (fp16 single-term)
    gemm_f16<<<dim3(NQKV_ / 128, TOK_ / 128), 256, GEMM_DYNSMEM>>>(
        Ah, Wh, QKV, TOK_, NQKV_, D_);

    // Fused RoPE + fp16 pack of Q/K/V
    rope_pack<<<(TOK_ * 48 * 64) / 256, 256>>>(QKV, cosp, sinp, Qh, Kh, Vh);

    // Attention (single-term fp16) -> Ohf
    attn_f16<<<dim3(S_ / 128, NH_, B_), 256, ATT_SMEM>>>(Qh, Kh, Vh, Ohf);

    // Output projection (fp16 single-term)
    gemm_f16<<<dim3(D_ / 128, TOK_ / 128), 256, GEMM_DYNSMEM>>>(
        Ohf, WOh, out, TOK_, D_, NH_ * HD_);
}